// round 5
// baseline (speedup 1.0000x reference)
#include <cuda_runtime.h>
#include <cuda_bf16.h>
#include <math.h>
#include <stdint.h>

#define B_ 64
#define S_ 1024
#define E_ 256
#define NQK (64ull * 1024 * 256)

// -------------------- device scratch (static .bss, no runtime alloc) --------
__device__ float          g_v  [NQK];                 // v fp32 [b][t][d]
__device__ __nv_bfloat16  g_xh [NQK], g_xl [NQK];     // x split [m][e]
__device__ __nv_bfloat16  g_wth[3 * 256 * 256], g_wtl[3 * 256 * 256];  // W^T split
__device__ __nv_bfloat16  g_qh [NQK], g_ql[NQK];
__device__ __nv_bfloat16  g_kh [NQK], g_kl[NQK];
__device__ __nv_bfloat16  g_vth[NQK], g_vtl[NQK];     // vT [b][d][t]

union BP8 { __nv_bfloat16 b[8]; uint4 u; };
union BP4 { __nv_bfloat16 b[4]; uint2 u; };

// ---------------- base-target PTX helpers (sm_80+ features only) ------------
__device__ __forceinline__ uint32_t smem_u32(const void* p) {
    uint32_t a;
    asm("{ .reg .u64 t; cvta.to.shared.u64 t, %1; cvt.u32.u64 %0, t; }" : "=r"(a) : "l"(p));
    return a;
}
__device__ __forceinline__ void cpa16(uint32_t saddr, const void* g) {
    asm volatile("cp.async.cg.shared.global [%0], [%1], 16;" :: "r"(saddr), "l"(g));
}
#define CPA_COMMIT() asm volatile("cp.async.commit_group;" ::: "memory")
#define CPA_WAIT1()  asm volatile("cp.async.wait_group 1;" ::: "memory")

__device__ __forceinline__ void ldsm_x4(uint32_t* r, uint32_t addr) {
    asm volatile("ldmatrix.sync.aligned.m8n8.x4.shared.b16 {%0,%1,%2,%3}, [%4];"
                 : "=r"(r[0]), "=r"(r[1]), "=r"(r[2]), "=r"(r[3]) : "r"(addr));
}
__device__ __forceinline__ void mma16816(float* c, const uint32_t* a, const uint32_t* b) {
    asm volatile(
        "mma.sync.aligned.m16n8k16.row.col.f32.bf16.bf16.f32 "
        "{%0,%1,%2,%3}, {%4,%5,%6,%7}, {%8,%9}, {%0,%1,%2,%3};"
        : "+f"(c[0]), "+f"(c[1]), "+f"(c[2]), "+f"(c[3])
        : "r"(a[0]), "r"(a[1]), "r"(a[2]), "r"(a[3]), "r"(b[0]), "r"(b[1]));
}

__device__ __forceinline__ void store_hilo2(__nv_bfloat16* dh, __nv_bfloat16* dl,
                                            float a, float b) {
    __nv_bfloat16 ha = __float2bfloat16_rn(a), hb = __float2bfloat16_rn(b);
    __nv_bfloat162 hp; hp.x = ha; hp.y = hb;
    __nv_bfloat162 lp;
    lp.x = __float2bfloat16_rn(a - __bfloat162float(ha));
    lp.y = __float2bfloat16_rn(b - __bfloat162float(hb));
    *(__nv_bfloat162*)dh = hp;
    *(__nv_bfloat162*)dl = lp;
}

__device__ __forceinline__ float fast_exp(float x) {   // x <= 0
    float y = x * 1.4426950408889634f;
    float n = rintf(y);
    float t = (y - n) * 0.6931471805599453f;
    float p = 1.9841270e-4f;
    p = fmaf(p, t, 1.3888889e-3f);
    p = fmaf(p, t, 8.3333333e-3f);
    p = fmaf(p, t, 4.1666667e-2f);
    p = fmaf(p, t, 0.16666667f);
    p = fmaf(p, t, 0.5f);
    p = fmaf(p, t, 1.0f);
    p = fmaf(p, t, 1.0f);
    float r = __int_as_float(__float_as_int(p) + ((int)n << 23));
    return (x > -87.0f) ? r : 0.0f;
}

// ============================================================================
// Triple-bf16 HMMA GEMM used for QKV projection only (EPI 1).
// ============================================================================
#define GSM_BYTES (2 * 65536 + 128)

template<int NCH, int NTOT, int EPI>
__global__ __launch_bounds__(256) void gemm3_mma(
    const __nv_bfloat16* __restrict__ Ah_, const __nv_bfloat16* __restrict__ Al_,
    const __nv_bfloat16* __restrict__ Bh_, const __nv_bfloat16* __restrict__ Bl_,
    float* __restrict__ C,
    const float* __restrict__ bq, const float* __restrict__ bk,
    const float* __restrict__ bv,
    long long aBatch, long long bBatch, long long cBatch, int lda, int ldb) {
    extern __shared__ char dsm[];
    char* sb = (char*)(((uintptr_t)dsm + 127) & ~(uintptr_t)127);
    const uint32_t sbase = smem_u32(sb);

    const int tid = threadIdx.x;
    const int wid = tid >> 5, lane = tid & 31;
    const int z = blockIdx.z;
    const int m0 = blockIdx.x * 128, n0 = blockIdx.y * 128;

    const __nv_bfloat16* gA[2] = { Ah_ + (size_t)z * aBatch + (size_t)m0 * lda,
                                   Al_ + (size_t)z * aBatch + (size_t)m0 * lda };
    const __nv_bfloat16* gB[2] = { Bh_ + (size_t)z * bBatch + (size_t)n0 * ldb,
                                   Bl_ + (size_t)z * bBatch + (size_t)n0 * ldb };

    const int lrow = tid >> 3, lkg = tid & 7;

    const int wm = wid & 3, wn = wid >> 2;
    const int li = lane >> 3, lr = lane & 7;
    const int arow = wm * 32 + (li & 1) * 8 + lr;
    const int brow = wn * 64 + (li & 1) * 8 + lr;
    const int kgh = li >> 1;

    float acc[2][8][4];
#pragma unroll
    for (int im = 0; im < 2; im++)
#pragma unroll
        for (int j = 0; j < 8; j++)
#pragma unroll
            for (int q = 0; q < 4; q++) acc[im][j][q] = 0.0f;

#define LOAD_STAGE(kc, st) do {                                                  \
        uint32_t s0_ = sbase + (st) * 65536;                                     \
        _Pragma("unroll")                                                        \
        for (int m_ = 0; m_ < 4; m_++) {                                         \
            const __nv_bfloat16* src_ = (m_ < 2) ? gA[m_] : gB[m_ - 2];          \
            int ld_ = (m_ < 2) ? lda : ldb;                                      \
            _Pragma("unroll")                                                    \
            for (int p_ = 0; p_ < 4; p_++) {                                     \
                int row_ = lrow + p_ * 32;                                       \
                cpa16(s0_ + m_ * 16384 + row_ * 128 + ((lkg ^ (row_ & 7)) << 4), \
                      src_ + (size_t)row_ * ld_ + (kc) * 64 + lkg * 8);          \
            }                                                                    \
        }                                                                        \
    } while (0)

    LOAD_STAGE(0, 0); CPA_COMMIT();
    LOAD_STAGE(1, 1); CPA_COMMIT();

    for (int kc = 0; kc < NCH; kc++) {
        CPA_WAIT1();
        __syncthreads();
        const uint32_t s0 = sbase + (kc & 1) * 65536;
#pragma unroll
        for (int kt = 0; kt < 4; kt++) {
            const int kg = kt * 2 + kgh;
            uint32_t ah[2][4], al[2][4], bh[4][4], bl[4][4];
#pragma unroll
            for (int im = 0; im < 2; im++) {
                int m_l = arow + im * 16;
                uint32_t ad = s0 + m_l * 128 + ((kg ^ (m_l & 7)) << 4);
                ldsm_x4(ah[im], ad);
                ldsm_x4(al[im], ad + 16384);
            }
#pragma unroll
            for (int jn = 0; jn < 4; jn++) {
                int n_l = brow + jn * 16;
                uint32_t bd = s0 + 32768 + n_l * 128 + ((kg ^ (n_l & 7)) << 4);
                ldsm_x4(bh[jn], bd);
                ldsm_x4(bl[jn], bd + 16384);
            }
#pragma unroll
            for (int im = 0; im < 2; im++)
#pragma unroll
                for (int j8 = 0; j8 < 8; j8++) {
                    uint32_t bfh[2] = { bh[j8 >> 1][j8 & 1], bh[j8 >> 1][(j8 & 1) + 2] };
                    uint32_t bfl[2] = { bl[j8 >> 1][j8 & 1], bl[j8 >> 1][(j8 & 1) + 2] };
                    mma16816(acc[im][j8], ah[im], bfh);
                    mma16816(acc[im][j8], ah[im], bfl);
                    mma16816(acc[im][j8], al[im], bfh);
                }
        }
        __syncthreads();
        if (kc + 2 < NCH) LOAD_STAGE(kc + 2, kc & 1);
        CPA_COMMIT();
    }
#undef LOAD_STAGE

    const int erow = wm * 32 + (lane >> 2);
    const int ecol = wn * 64 + 2 * (lane & 3);
    if (EPI == 0) {
        float* Cb = C + (size_t)z * cBatch;
#pragma unroll
        for (int im = 0; im < 2; im++)
#pragma unroll
            for (int j8 = 0; j8 < 8; j8++) {
                int rr = m0 + erow + im * 16;
                int cc = n0 + ecol + j8 * 8;
                *(float2*)&Cb[(size_t)rr * NTOT + cc] =
                    make_float2(acc[im][j8][0], acc[im][j8][1]);
                *(float2*)&Cb[(size_t)(rr + 8) * NTOT + cc] =
                    make_float2(acc[im][j8][2], acc[im][j8][3]);
            }
    } else {
        const float* bias = (z == 0) ? bq : (z == 1) ? bk : bv;
#pragma unroll
        for (int im = 0; im < 2; im++)
#pragma unroll
            for (int j8 = 0; j8 < 8; j8++) {
                int rr = m0 + erow + im * 16;
                int cc = n0 + ecol + j8 * 8;
                float b0v = bias[cc], b1v = bias[cc + 1];
                float v00 = acc[im][j8][0] + b0v, v01 = acc[im][j8][1] + b1v;
                float v10 = acc[im][j8][2] + b0v, v11 = acc[im][j8][3] + b1v;
                if (z == 2) {
                    *(float2*)&g_v[(size_t)rr * 256 + cc] = make_float2(v00, v01);
                    *(float2*)&g_v[(size_t)(rr + 8) * 256 + cc] = make_float2(v10, v11);
                } else {
                    __nv_bfloat16* dh = (z == 0) ? g_qh : g_kh;
                    __nv_bfloat16* dl = (z == 0) ? g_ql : g_kl;
                    store_hilo2(dh + (size_t)rr * 256 + cc, dl + (size_t)rr * 256 + cc, v00, v01);
                    store_hilo2(dh + (size_t)(rr + 8) * 256 + cc, dl + (size_t)(rr + 8) * 256 + cc, v10, v11);
                }
            }
    }
}

// ============================================================================
// split x -> bf16 hi/lo
// ============================================================================
__global__ __launch_bounds__(256) void split_x_kernel(const float* __restrict__ x) {
    size_t i = ((size_t)blockIdx.x * 256 + threadIdx.x) * 4;
    float4 v = *(const float4*)&x[i];
    float f[4] = { v.x, v.y, v.z, v.w };
    BP4 hp, lp;
#pragma unroll
    for (int j = 0; j < 4; j++) {
        hp.b[j] = __float2bfloat16_rn(f[j]);
        lp.b[j] = __float2bfloat16_rn(f[j] - __bfloat162float(hp.b[j]));
    }
    *(uint2*)&g_xh[i] = hp.u;
    *(uint2*)&g_xl[i] = lp.u;
}

// ============================================================================
// transpose + split W (256x256, [e][n] -> [n][e] hi/lo), z = which W
// ============================================================================
__global__ __launch_bounds__(256) void splitT_w_kernel(
    const float* __restrict__ Wq, const float* __restrict__ Wk,
    const float* __restrict__ Wv) {
    __shared__ float ts[64 * 65];
    const float* W = (blockIdx.z == 0) ? Wq : (blockIdx.z == 1) ? Wk : Wv;
    const int e0 = blockIdx.x * 64, n0 = blockIdx.y * 64;
    const int tid = threadIdx.x;
    const size_t zo = (size_t)blockIdx.z * 65536;

#pragma unroll
    for (int p = 0; p < 4; p++) {
        int idx = tid + p * 256;
        int r = idx >> 4, c4 = idx & 15;
        float4 v = *(const float4*)&W[(size_t)(e0 + r) * 256 + n0 + c4 * 4];
        ts[r * 65 + c4 * 4 + 0] = v.x; ts[r * 65 + c4 * 4 + 1] = v.y;
        ts[r * 65 + c4 * 4 + 2] = v.z; ts[r * 65 + c4 * 4 + 3] = v.w;
    }
    __syncthreads();
#pragma unroll
    for (int p = 0; p < 2; p++) {
        int idx = tid + p * 256;
        int nl = idx >> 3, tc = idx & 7;
        BP8 hp, lp;
#pragma unroll
        for (int j = 0; j < 8; j++) {
            float v = ts[(tc * 8 + j) * 65 + nl];
            hp.b[j] = __float2bfloat16_rn(v);
            lp.b[j] = __float2bfloat16_rn(v - __bfloat162float(hp.b[j]));
        }
        size_t di = zo + (size_t)(n0 + nl) * 256 + e0 + tc * 8;
        *(uint4*)&g_wth[di] = hp.u;
        *(uint4*)&g_wtl[di] = lp.u;
    }
}

// ============================================================================
// transpose + split v -> vT hi/lo.  grid (16 t-tiles, 4 d-tiles, 64 b)
// ============================================================================
__global__ __launch_bounds__(256) void conv_vT_kernel() {
    __shared__ float ts[64 * 65];
    const int tid = threadIdx.x;
    const int t0 = blockIdx.x * 64, d0 = blockIdx.y * 64, b = blockIdx.z;

#pragma unroll
    for (int p = 0; p < 4; p++) {
        int idx = tid + p * 256;
        int r = idx >> 4, c4 = idx & 15;
        float4 v = *(const float4*)&g_v[((size_t)(b << 10) + t0 + r) * 256 + d0 + c4 * 4];
        ts[r * 65 + c4 * 4 + 0] = v.x; ts[r * 65 + c4 * 4 + 1] = v.y;
        ts[r * 65 + c4 * 4 + 2] = v.z; ts[r * 65 + c4 * 4 + 3] = v.w;
    }
    __syncthreads();
#pragma unroll
    for (int p = 0; p < 2; p++) {
        int idx = tid + p * 256;
        int dl = idx >> 3, tc = idx & 7;
        BP8 hp, lp;
#pragma unroll
        for (int j = 0; j < 8; j++) {
            float v = ts[(tc * 8 + j) * 65 + dl];
            hp.b[j] = __float2bfloat16_rn(v);
            lp.b[j] = __float2bfloat16_rn(v - __bfloat162float(hp.b[j]));
        }
        size_t di = ((size_t)b * 256 + d0 + dl) * 1024 + t0 + tc * 8;
        *(uint4*)&g_vth[di] = hp.u;
        *(uint4*)&g_vtl[di] = lp.u;
    }
}

// ============================================================================
// Fused flash attention: scores(bf16x3) + online softmax + AV(bf16x3).
// CTA = 64 queries x d=256, Bc=32 keys/iter, 32 iters, 8 warps (4m x 2n).
// SMEM: Q hi/lo 64KB persistent (swizzled 512B rows), K/V hi/lo double-buffered
// (72KB/stage; vT rows pitch 80B -> conflict-free ldsm), P hi/lo 10KB staging,
// 1KB reduction scratch.  O stays in registers (64 fp32/thread).
// ============================================================================
#define FSQH   0
#define FSQL   32768
#define FSTG0  65536
#define FSTG_SZ 73728            // Kh 16K | Kl 16K | Vh 20K | Vl 20K
#define FVH    32768
#define FRED   212992            // sRedM[128] floats
#define FREDS  213504            // sRedS[128] floats
#define FSPH   214016            // P_hi 64 x pitch40 bf16 = 5120B
#define FSPL   219136
#define FSM_TOTAL 224256

__global__ __launch_bounds__(256) void flash_kernel(float* __restrict__ out) {
    extern __shared__ __align__(1024) char fsm[];
    const uint32_t sb = smem_u32(fsm);
    const int tid = threadIdx.x;
    const int wid = tid >> 5, lane = tid & 31;
    const int wm = wid & 3, wn = wid >> 2;
    const int li = lane >> 3, lr = lane & 7;
    const int r = lane >> 2, qq = lane & 3;
    const int b = blockIdx.y, q0 = blockIdx.x * 64;

    const int arow = wm * 16 + (li & 1) * 8 + lr;   // q row for ldsm A
    const int brow = wn * 16 + (li & 1) * 8 + lr;   // key row for ldsm B (scores)
    const uint32_t kh16 = (uint32_t)(li >> 1) << 4; // 16B half select

    float accO[16][4];
#pragma unroll
    for (int t = 0; t < 16; t++)
#pragma unroll
        for (int j = 0; j < 4; j++) accO[t][j] = 0.0f;
    float m0r = -3.0e38f, m8r = -3.0e38f, l0r = 0.0f, l8r = 0.0f;

#define LOAD_KV(t0_, st_) do {                                                   \
        uint32_t stg_ = sb + FSTG0 + (st_) * FSTG_SZ;                            \
        _Pragma("unroll")                                                        \
        for (int p_ = 0; p_ < 8; p_++) {                                         \
            int idx_ = tid + p_ * 256;                                           \
            int mat_ = idx_ >> 10, rem_ = idx_ & 1023;                           \
            int row_ = rem_ >> 5, c16_ = rem_ & 31;                              \
            const __nv_bfloat16* src_ = (mat_ ? g_kl : g_kh) +                   \
                ((size_t)(b << 10) + (t0_) + row_) * 256 + c16_ * 8;             \
            cpa16(stg_ + mat_ * 16384 + row_ * 512 +                             \
                  ((((c16_ >> 1) ^ (row_ & 7)) << 5) | ((c16_ & 1) << 4)), src_);\
        }                                                                        \
        _Pragma("unroll")                                                        \
        for (int p_ = 0; p_ < 8; p_++) {                                         \
            int idx_ = tid + p_ * 256;                                           \
            int mat_ = idx_ >> 10, rem_ = idx_ & 1023;                           \
            int d_ = rem_ >> 2, c16_ = rem_ & 3;                                 \
            const __nv_bfloat16* src_ = (mat_ ? g_vtl : g_vth) +                 \
                ((size_t)b * 256 + d_) * 1024 + (t0_) + c16_ * 8;                \
            cpa16(stg_ + FVH + mat_ * 20480 + d_ * 80 + c16_ * 16, src_);        \
        }                                                                        \
    } while (0)

    // ---- prologue: Q (persistent) + first two K/V stages ----
#pragma unroll
    for (int p = 0; p < 16; p++) {
        int idx = tid + p * 256;
        int mat = idx >> 11, rem = idx & 2047;
        int row = rem >> 5, c16 = rem & 31;
        const __nv_bfloat16* src = (mat ? g_ql : g_qh) +
            ((size_t)(b << 10) + q0 + row) * 256 + c16 * 8;
        cpa16(sb + (mat ? FSQL : FSQH) + row * 512 +
              ((((c16 >> 1) ^ (row & 7)) << 5) | ((c16 & 1) << 4)), src);
    }
    LOAD_KV(0, 0);
    CPA_COMMIT();
    LOAD_KV(32, 1);
    CPA_COMMIT();

    float* sRedM = (float*)(fsm + FRED);
    float* sRedS = (float*)(fsm + FREDS);
    __nv_bfloat16* sPh = (__nv_bfloat16*)(fsm + FSPH);
    __nv_bfloat16* sPl = (__nv_bfloat16*)(fsm + FSPL);

    for (int it = 0; it < 32; it++) {
        CPA_WAIT1();
        __syncthreads();
        const uint32_t stg = sb + FSTG0 + (it & 1) * FSTG_SZ;

        // ---- scores: S(64x32) = Qh.Kh^T + Qh.Kl^T + Ql.Kh^T ----
        float accS[2][4] = {};
#pragma unroll
        for (int kt = 0; kt < 16; kt++) {
            uint32_t qa = sb + FSQH + arow * 512 + (((uint32_t)(kt ^ (arow & 7)) << 5) | kh16);
            uint32_t ka = stg + brow * 512 + (((uint32_t)(kt ^ (brow & 7)) << 5) | kh16);
            uint32_t qh_[4], ql_[4], kh_[4], kl_[4];
            ldsm_x4(qh_, qa); ldsm_x4(ql_, qa + 32768);
            ldsm_x4(kh_, ka); ldsm_x4(kl_, ka + 16384);
#pragma unroll
            for (int j = 0; j < 2; j++) {
                uint32_t b2h[2] = { kh_[j], kh_[j + 2] };
                uint32_t b2l[2] = { kl_[j], kl_[j + 2] };
                mma16816(accS[j], qh_, b2h);
                mma16816(accS[j], qh_, b2l);
                mma16816(accS[j], ql_, b2h);
            }
        }

        // ---- online softmax (cross-warp via SMEM) ----
        const int row0 = wm * 16 + r;
        float v00 = accS[0][0], v01 = accS[0][1], v10 = accS[1][0], v11 = accS[1][1];
        float w00 = accS[0][2], w01 = accS[0][3], w10 = accS[1][2], w11 = accS[1][3];
        float mx0 = fmaxf(fmaxf(v00, v01), fmaxf(v10, v11));
        float mx8 = fmaxf(fmaxf(w00, w01), fmaxf(w10, w11));
        mx0 = fmaxf(mx0, __shfl_xor_sync(0xffffffffu, mx0, 1));
        mx0 = fmaxf(mx0, __shfl_xor_sync(0xffffffffu, mx0, 2));
        mx8 = fmaxf(mx8, __shfl_xor_sync(0xffffffffu, mx8, 1));
        mx8 = fmaxf(mx8, __shfl_xor_sync(0xffffffffu, mx8, 2));
        if (qq == 0) {
            sRedM[wn * 64 + row0] = mx0;
            sRedM[wn * 64 + row0 + 8] = mx8;
        }
        __syncthreads();
        float tm0 = fmaxf(sRedM[row0], sRedM[64 + row0]);
        float tm8 = fmaxf(sRedM[row0 + 8], sRedM[64 + row0 + 8]);
        float mn0 = fmaxf(m0r, tm0), mn8 = fmaxf(m8r, tm8);
        float cor0 = fast_exp(m0r - mn0), cor8 = fast_exp(m8r - mn8);
        float p00 = fast_exp(v00 - mn0), p01 = fast_exp(v01 - mn0);
        float p10 = fast_exp(v10 - mn0), p11 = fast_exp(v11 - mn0);
        float e00 = fast_exp(w00 - mn8), e01 = fast_exp(w01 - mn8);
        float e10 = fast_exp(w10 - mn8), e11 = fast_exp(w11 - mn8);
        float s0 = (p00 + p01) + (p10 + p11);
        float s8 = (e00 + e01) + (e10 + e11);
        s0 += __shfl_xor_sync(0xffffffffu, s0, 1);
        s0 += __shfl_xor_sync(0xffffffffu, s0, 2);
        s8 += __shfl_xor_sync(0xffffffffu, s8, 1);
        s8 += __shfl_xor_sync(0xffffffffu, s8, 2);
        if (qq == 0) {
            sRedS[wn * 64 + row0] = s0;
            sRedS[wn * 64 + row0 + 8] = s8;
        }
        {   // write P hi/lo to staging (pitch 40 bf16 rows)
            int cb = wn * 16 + 2 * qq;
            store_hilo2(&sPh[row0 * 40 + cb],     &sPl[row0 * 40 + cb],     p00, p01);
            store_hilo2(&sPh[row0 * 40 + cb + 8], &sPl[row0 * 40 + cb + 8], p10, p11);
            store_hilo2(&sPh[(row0 + 8) * 40 + cb],     &sPl[(row0 + 8) * 40 + cb],     e00, e01);
            store_hilo2(&sPh[(row0 + 8) * 40 + cb + 8], &sPl[(row0 + 8) * 40 + cb + 8], e10, e11);
        }
        __syncthreads();
        float lt0 = sRedS[row0] + sRedS[64 + row0];
        float lt8 = sRedS[row0 + 8] + sRedS[64 + row0 + 8];
        l0r = l0r * cor0 + lt0;
        l8r = l8r * cor8 + lt8;
        m0r = mn0; m8r = mn8;
#pragma unroll
        for (int t = 0; t < 16; t++) {
            accO[t][0] *= cor0; accO[t][1] *= cor0;
            accO[t][2] *= cor8; accO[t][3] *= cor8;
        }

        // ---- AV: O(64x256) += Ph.Vh + Ph.Vl + Pl.Vh  (V as vT[d][t]) ----
        const int prow = wm * 16 + (li & 1) * 8 + lr;
#pragma unroll
        for (int ktile = 0; ktile < 2; ktile++) {
            uint32_t pa = sb + FSPH + prow * 80 + ktile * 32 + kh16;
            uint32_t ph_[4], pl_[4];
            ldsm_x4(ph_, pa);
            ldsm_x4(pl_, pa + 5120);
#pragma unroll
            for (int nt = 0; nt < 8; nt++) {
                int d_l = wn * 128 + nt * 16 + (li & 1) * 8 + lr;
                uint32_t va = stg + FVH + d_l * 80 + ktile * 32 + kh16;
                uint32_t vh_[4], vl_[4];
                ldsm_x4(vh_, va);
                ldsm_x4(vl_, va + 20480);
#pragma unroll
                for (int j = 0; j < 2; j++) {
                    uint32_t b2h[2] = { vh_[j], vh_[j + 2] };
                    uint32_t b2l[2] = { vl_[j], vl_[j + 2] };
                    float* c = accO[nt * 2 + j];
                    mma16816(c, ph_, b2h);
                    mma16816(c, ph_, b2l);
                    mma16816(c, pl_, b2h);
                }
            }
        }
        __syncthreads();
        if (it + 2 < 32) LOAD_KV((it + 2) * 32, it & 1);
        CPA_COMMIT();
    }
#undef LOAD_KV

    // ---- epilogue: O / l -> out ----
    float li0 = 1.0f / l0r, li8 = 1.0f / l8r;
    float* base0 = out + ((size_t)(b << 10) + q0 + wm * 16 + r) * 256 + wn * 128 + 2 * qq;
    float* base8 = base0 + 8 * 256;
#pragma unroll
    for (int t = 0; t < 16; t++) {
        *(float2*)(base0 + t * 8) = make_float2(accO[t][0] * li0, accO[t][1] * li0);
        *(float2*)(base8 + t * 8) = make_float2(accO[t][2] * li8, accO[t][3] * li8);
    }
}

// ============================================================================
extern "C" void kernel_launch(void* const* d_in, const int* in_sizes, int n_in,
                              void* d_out, int out_size) {
    const float* x  = (const float*)d_in[0];
    const float* Wq = (const float*)d_in[1];
    const float* bq = (const float*)d_in[2];
    const float* Wk = (const float*)d_in[3];
    const float* bk = (const float*)d_in[4];
    const float* Wv = (const float*)d_in[5];
    const float* bv = (const float*)d_in[6];
    float* out = (float*)d_out;

    void *axh, *axl, *awth, *awtl, *av;
    cudaGetSymbolAddress(&axh, g_xh);   cudaGetSymbolAddress(&axl, g_xl);
    cudaGetSymbolAddress(&awth, g_wth); cudaGetSymbolAddress(&awtl, g_wtl);
    cudaGetSymbolAddress(&av, g_v);

    cudaFuncSetAttribute(gemm3_mma<4, 256, 1>,
                         cudaFuncAttributeMaxDynamicSharedMemorySize, GSM_BYTES);
    cudaFuncSetAttribute(flash_kernel,
                         cudaFuncAttributeMaxDynamicSharedMemorySize, FSM_TOTAL);

    // 1. split inputs
    split_x_kernel<<<16384, 256>>>(x);
    splitT_w_kernel<<<dim3(4, 4, 3), 256>>>(Wq, Wk, Wv);

    // 2. QKV projection (bf16x3 HMMA): writes qh/ql, kh/kl, v
    gemm3_mma<4, 256, 1><<<dim3(512, 2, 3), 256, GSM_BYTES>>>(
        (const __nv_bfloat16*)axh, (const __nv_bfloat16*)axl,
        (const __nv_bfloat16*)awth, (const __nv_bfloat16*)awtl,
        (float*)av, bq, bk, bv,
        0LL, 65536LL, 0LL, 256, 256);

    // 3. v -> vT hi/lo
    conv_vT_kernel<<<dim3(16, 4, 64), 256>>>();

    // 4. fused flash attention -> out
    flash_kernel<<<dim3(16, 64), 256, FSM_TOTAL>>>(out);
}

// round 8
// speedup vs baseline: 1.3028x; 1.3028x over previous
#include <cuda_runtime.h>
#include <cuda_bf16.h>
#include <math.h>
#include <stdint.h>

#define B_ 64
#define S_ 1024
#define E_ 256
#define NQK (64ull * 1024 * 256)
#define NP  (64ull * 1024 * 1024)

// -------------------- device scratch (static .bss, no runtime alloc) --------
__device__ float          g_v  [NQK];                 // v fp32 [b][t][d]
__device__ __nv_bfloat16  g_xh [NQK], g_xl [NQK];     // x split [m][e]
__device__ __nv_bfloat16  g_wth[3 * 256 * 256], g_wtl[3 * 256 * 256];  // W^T split
__device__ __nv_bfloat16  g_qh [NQK], g_ql[NQK];
__device__ __nv_bfloat16  g_kh [NQK], g_kl[NQK];
__device__ __nv_bfloat16  g_vth[NQK], g_vtl[NQK];     // vT [b][d][t]
__device__ __nv_bfloat16  g_ph [NP],  g_pl [NP];      // exp(s-60) hi/lo [b][q][t]
__device__ float          g_lpart[64 * 16 * 1024];    // partial row sums [b][t16][q]
__device__ float          g_l  [64 * 1024];           // row sums [b][q]

union BP8 { __nv_bfloat16 b[8]; uint4 u; };
union BP4 { __nv_bfloat16 b[4]; uint2 u; };

// ---------------- base-target PTX helpers (sm_80+ features only) ------------
__device__ __forceinline__ uint32_t smem_u32(const void* p) {
    uint32_t a;
    asm("{ .reg .u64 t; cvta.to.shared.u64 t, %1; cvt.u32.u64 %0, t; }" : "=r"(a) : "l"(p));
    return a;
}
__device__ __forceinline__ void cpa16(uint32_t saddr, const void* g) {
    asm volatile("cp.async.cg.shared.global [%0], [%1], 16;" :: "r"(saddr), "l"(g));
}
#define CPA_COMMIT() asm volatile("cp.async.commit_group;" ::: "memory")
#define CPA_WAIT1()  asm volatile("cp.async.wait_group 1;" ::: "memory")

__device__ __forceinline__ void ldsm_x4(uint32_t* r, uint32_t addr) {
    asm volatile("ldmatrix.sync.aligned.m8n8.x4.shared.b16 {%0,%1,%2,%3}, [%4];"
                 : "=r"(r[0]), "=r"(r[1]), "=r"(r[2]), "=r"(r[3]) : "r"(addr));
}
__device__ __forceinline__ void mma16816(float* c, const uint32_t* a, const uint32_t* b) {
    asm volatile(
        "mma.sync.aligned.m16n8k16.row.col.f32.bf16.bf16.f32 "
        "{%0,%1,%2,%3}, {%4,%5,%6,%7}, {%8,%9}, {%0,%1,%2,%3};"
        : "+f"(c[0]), "+f"(c[1]), "+f"(c[2]), "+f"(c[3])
        : "r"(a[0]), "r"(a[1]), "r"(a[2]), "r"(a[3]), "r"(b[0]), "r"(b[1]));
}

__device__ __forceinline__ void store_hilo2(__nv_bfloat16* dh, __nv_bfloat16* dl,
                                            float a, float b) {
    __nv_bfloat16 ha = __float2bfloat16_rn(a), hb = __float2bfloat16_rn(b);
    __nv_bfloat162 hp; hp.x = ha; hp.y = hb;
    __nv_bfloat162 lp;
    lp.x = __float2bfloat16_rn(a - __bfloat162float(ha));
    lp.y = __float2bfloat16_rn(b - __bfloat162float(hb));
    *(__nv_bfloat162*)dh = hp;
    *(__nv_bfloat162*)dl = lp;
}

__device__ __forceinline__ float fast_exp(float x) {   // accurate over [-87, +40]
    float y = x * 1.4426950408889634f;
    float n = rintf(y);
    float t = (y - n) * 0.6931471805599453f;
    float p = 1.9841270e-4f;
    p = fmaf(p, t, 1.3888889e-3f);
    p = fmaf(p, t, 8.3333333e-3f);
    p = fmaf(p, t, 4.1666667e-2f);
    p = fmaf(p, t, 0.16666667f);
    p = fmaf(p, t, 0.5f);
    p = fmaf(p, t, 1.0f);
    p = fmaf(p, t, 1.0f);
    float r = __int_as_float(__float_as_int(p) + ((int)n << 23));
    return (x > -87.0f) ? r : 0.0f;
}

// ============================================================================
// Triple-bf16 HMMA GEMM: D = Ah.Bh^T + Ah.Bl^T + Al.Bh^T  (fp32 accum)
// CTA tile 128x128, k-chunk 64, 8 warps (4m x 2n), cp.async double-buffered.
// EPI 1: proj epilogue (bias + hi/lo split / v fp32)
// EPI 2: scores epilogue (exp(s-60) -> P hi/lo + deterministic partial row sums)
// EPI 3: AV epilogue (divide by row sum, store to out)
// ============================================================================
#define GSM_BYTES (2 * 65536 + 128)

template<int NCH, int NTOT, int EPI>
__global__ __launch_bounds__(256) void gemm3_mma(
    const __nv_bfloat16* __restrict__ Ah_, const __nv_bfloat16* __restrict__ Al_,
    const __nv_bfloat16* __restrict__ Bh_, const __nv_bfloat16* __restrict__ Bl_,
    float* __restrict__ C,
    const float* __restrict__ bq, const float* __restrict__ bk,
    const float* __restrict__ bv,
    long long aBatch, long long bBatch, long long cBatch, int lda, int ldb) {
    extern __shared__ char dsm[];
    char* sb = (char*)(((uintptr_t)dsm + 127) & ~(uintptr_t)127);
    const uint32_t sbase = smem_u32(sb);

    const int tid = threadIdx.x;
    const int wid = tid >> 5, lane = tid & 31;
    const int z = blockIdx.z;
    const int m0 = blockIdx.x * 128, n0 = blockIdx.y * 128;

    const __nv_bfloat16* gA[2] = { Ah_ + (size_t)z * aBatch + (size_t)m0 * lda,
                                   Al_ + (size_t)z * aBatch + (size_t)m0 * lda };
    const __nv_bfloat16* gB[2] = { Bh_ + (size_t)z * bBatch + (size_t)n0 * ldb,
                                   Bl_ + (size_t)z * bBatch + (size_t)n0 * ldb };

    const int lrow = tid >> 3, lkg = tid & 7;

    const int wm = wid & 3, wn = wid >> 2;
    const int li = lane >> 3, lr = lane & 7;
    const int arow = wm * 32 + (li & 1) * 8 + lr;
    const int brow = wn * 64 + (li & 1) * 8 + lr;
    const int kgh = li >> 1;

    float acc[2][8][4];
#pragma unroll
    for (int im = 0; im < 2; im++)
#pragma unroll
        for (int j = 0; j < 8; j++)
#pragma unroll
            for (int q = 0; q < 4; q++) acc[im][j][q] = 0.0f;

#define LOAD_STAGE(kc, st) do {                                                  \
        uint32_t s0_ = sbase + (st) * 65536;                                     \
        _Pragma("unroll")                                                        \
        for (int m_ = 0; m_ < 4; m_++) {                                         \
            const __nv_bfloat16* src_ = (m_ < 2) ? gA[m_] : gB[m_ - 2];          \
            int ld_ = (m_ < 2) ? lda : ldb;                                      \
            _Pragma("unroll")                                                    \
            for (int p_ = 0; p_ < 4; p_++) {                                     \
                int row_ = lrow + p_ * 32;                                       \
                cpa16(s0_ + m_ * 16384 + row_ * 128 + ((lkg ^ (row_ & 7)) << 4), \
                      src_ + (size_t)row_ * ld_ + (kc) * 64 + lkg * 8);          \
            }                                                                    \
        }                                                                        \
    } while (0)

    LOAD_STAGE(0, 0); CPA_COMMIT();
    LOAD_STAGE(1, 1); CPA_COMMIT();

    for (int kc = 0; kc < NCH; kc++) {
        CPA_WAIT1();
        __syncthreads();
        const uint32_t s0 = sbase + (kc & 1) * 65536;
#pragma unroll
        for (int kt = 0; kt < 4; kt++) {
            const int kg = kt * 2 + kgh;
            uint32_t ah[2][4], al[2][4], bh[4][4], bl[4][4];
#pragma unroll
            for (int im = 0; im < 2; im++) {
                int m_l = arow + im * 16;
                uint32_t ad = s0 + m_l * 128 + ((kg ^ (m_l & 7)) << 4);
                ldsm_x4(ah[im], ad);
                ldsm_x4(al[im], ad + 16384);
            }
#pragma unroll
            for (int jn = 0; jn < 4; jn++) {
                int n_l = brow + jn * 16;
                uint32_t bd = s0 + 32768 + n_l * 128 + ((kg ^ (n_l & 7)) << 4);
                ldsm_x4(bh[jn], bd);
                ldsm_x4(bl[jn], bd + 16384);
            }
#pragma unroll
            for (int im = 0; im < 2; im++)
#pragma unroll
                for (int j8 = 0; j8 < 8; j8++) {
                    uint32_t bfh[2] = { bh[j8 >> 1][j8 & 1], bh[j8 >> 1][(j8 & 1) + 2] };
                    uint32_t bfl[2] = { bl[j8 >> 1][j8 & 1], bl[j8 >> 1][(j8 & 1) + 2] };
                    mma16816(acc[im][j8], ah[im], bfh);
                    mma16816(acc[im][j8], ah[im], bfl);
                    mma16816(acc[im][j8], al[im], bfh);
                }
        }
        __syncthreads();
        if (kc + 2 < NCH) LOAD_STAGE(kc + 2, kc & 1);
        CPA_COMMIT();
    }
#undef LOAD_STAGE

    const int erow = wm * 32 + (lane >> 2);
    const int ecol = wn * 64 + 2 * (lane & 3);

    if (EPI == 1) {
        // -------- projection epilogue: + bias, split (q,k) / fp32 (v) --------
        const float* bias = (z == 0) ? bq : (z == 1) ? bk : bv;
#pragma unroll
        for (int im = 0; im < 2; im++)
#pragma unroll
            for (int j8 = 0; j8 < 8; j8++) {
                int rr = m0 + erow + im * 16;
                int cc = n0 + ecol + j8 * 8;
                float b0v = bias[cc], b1v = bias[cc + 1];
                float v00 = acc[im][j8][0] + b0v, v01 = acc[im][j8][1] + b1v;
                float v10 = acc[im][j8][2] + b0v, v11 = acc[im][j8][3] + b1v;
                if (z == 2) {
                    *(float2*)&g_v[(size_t)rr * 256 + cc] = make_float2(v00, v01);
                    *(float2*)&g_v[(size_t)(rr + 8) * 256 + cc] = make_float2(v10, v11);
                } else {
                    __nv_bfloat16* dh = (z == 0) ? g_qh : g_kh;
                    __nv_bfloat16* dl = (z == 0) ? g_ql : g_kl;
                    store_hilo2(dh + (size_t)rr * 256 + cc, dl + (size_t)rr * 256 + cc, v00, v01);
                    store_hilo2(dh + (size_t)(rr + 8) * 256 + cc, dl + (size_t)(rr + 8) * 256 + cc, v10, v11);
                }
            }
    } else if (EPI == 2) {
        // -------- scores epilogue: exp(s - 60), split, partial row sums ------
        float srow[4] = { 0.0f, 0.0f, 0.0f, 0.0f };
#pragma unroll
        for (int im = 0; im < 2; im++)
#pragma unroll
            for (int j8 = 0; j8 < 8; j8++) {
                int rr = m0 + erow + im * 16;
                int cc = n0 + ecol + j8 * 8;
                float e0 = fast_exp(acc[im][j8][0] - 60.0f);
                float e1 = fast_exp(acc[im][j8][1] - 60.0f);
                float e2 = fast_exp(acc[im][j8][2] - 60.0f);
                float e3 = fast_exp(acc[im][j8][3] - 60.0f);
                size_t o0 = ((size_t)(z << 10) + rr) * 1024 + cc;
                size_t o8 = o0 + 8 * 1024;
                store_hilo2(g_ph + o0, g_pl + o0, e0, e1);
                store_hilo2(g_ph + o8, g_pl + o8, e2, e3);
                srow[im * 2 + 0] += e0 + e1;
                srow[im * 2 + 1] += e2 + e3;
            }
#pragma unroll
        for (int r4 = 0; r4 < 4; r4++) {
            float s = srow[r4];
            s += __shfl_xor_sync(0xffffffffu, s, 1);
            s += __shfl_xor_sync(0xffffffffu, s, 2);
            if ((lane & 3) == 0) {
                int row = m0 + erow + (r4 >> 1) * 16 + (r4 & 1) * 8;
                g_lpart[(((size_t)z * 16 + (n0 >> 6) + wn) << 10) + row] = s;
            }
        }
    } else {
        // -------- AV epilogue: normalize by row sum, store ctx ---------------
        float linv[4];
#pragma unroll
        for (int r4 = 0; r4 < 4; r4++)
            linv[r4] = 1.0f / g_l[(size_t)(z << 10) + m0 + erow + (r4 >> 1) * 16 + (r4 & 1) * 8];
        float* Cb = C + (size_t)z * cBatch;
#pragma unroll
        for (int im = 0; im < 2; im++)
#pragma unroll
            for (int j8 = 0; j8 < 8; j8++) {
                int rr = m0 + erow + im * 16;
                int cc = n0 + ecol + j8 * 8;
                *(float2*)&Cb[(size_t)rr * NTOT + cc] =
                    make_float2(acc[im][j8][0] * linv[im * 2], acc[im][j8][1] * linv[im * 2]);
                *(float2*)&Cb[(size_t)(rr + 8) * NTOT + cc] =
                    make_float2(acc[im][j8][2] * linv[im * 2 + 1], acc[im][j8][3] * linv[im * 2 + 1]);
            }
    }
}

// ============================================================================
// reduce partial row sums: g_l[b][q] = sum_16 g_lpart[b][t][q]
// ============================================================================
__global__ __launch_bounds__(256) void reduce_l_kernel() {
    const int b = blockIdx.x;
#pragma unroll
    for (int p = 0; p < 4; p++) {
        int r = threadIdx.x + p * 256;
        float s = 0.0f;
#pragma unroll
        for (int t = 0; t < 16; t++)
            s += g_lpart[(((size_t)b * 16 + t) << 10) + r];
        g_l[((size_t)b << 10) + r] = s;
    }
}

// ============================================================================
// split x -> bf16 hi/lo
// ============================================================================
__global__ __launch_bounds__(256) void split_x_kernel(const float* __restrict__ x) {
    size_t i = ((size_t)blockIdx.x * 256 + threadIdx.x) * 4;
    float4 v = *(const float4*)&x[i];
    float f[4] = { v.x, v.y, v.z, v.w };
    BP4 hp, lp;
#pragma unroll
    for (int j = 0; j < 4; j++) {
        hp.b[j] = __float2bfloat16_rn(f[j]);
        lp.b[j] = __float2bfloat16_rn(f[j] - __bfloat162float(hp.b[j]));
    }
    *(uint2*)&g_xh[i] = hp.u;
    *(uint2*)&g_xl[i] = lp.u;
}

// ============================================================================
// transpose + split W (256x256, [e][n] -> [n][e] hi/lo), z = which W
// ============================================================================
__global__ __launch_bounds__(256) void splitT_w_kernel(
    const float* __restrict__ Wq, const float* __restrict__ Wk,
    const float* __restrict__ Wv) {
    __shared__ float ts[64 * 65];
    const float* W = (blockIdx.z == 0) ? Wq : (blockIdx.z == 1) ? Wk : Wv;
    const int e0 = blockIdx.x * 64, n0 = blockIdx.y * 64;
    const int tid = threadIdx.x;
    const size_t zo = (size_t)blockIdx.z * 65536;

#pragma unroll
    for (int p = 0; p < 4; p++) {
        int idx = tid + p * 256;
        int r = idx >> 4, c4 = idx & 15;
        float4 v = *(const float4*)&W[(size_t)(e0 + r) * 256 + n0 + c4 * 4];
        ts[r * 65 + c4 * 4 + 0] = v.x; ts[r * 65 + c4 * 4 + 1] = v.y;
        ts[r * 65 + c4 * 4 + 2] = v.z; ts[r * 65 + c4 * 4 + 3] = v.w;
    }
    __syncthreads();
#pragma unroll
    for (int p = 0; p < 2; p++) {
        int idx = tid + p * 256;
        int nl = idx >> 3, tc = idx & 7;
        BP8 hp, lp;
#pragma unroll
        for (int j = 0; j < 8; j++) {
            float v = ts[(tc * 8 + j) * 65 + nl];
            hp.b[j] = __float2bfloat16_rn(v);
            lp.b[j] = __float2bfloat16_rn(v - __bfloat162float(hp.b[j]));
        }
        size_t di = zo + (size_t)(n0 + nl) * 256 + e0 + tc * 8;
        *(uint4*)&g_wth[di] = hp.u;
        *(uint4*)&g_wtl[di] = lp.u;
    }
}

// ============================================================================
// transpose + split v -> vT hi/lo.  grid (16 t-tiles, 4 d-tiles, 64 b)
// ============================================================================
__global__ __launch_bounds__(256) void conv_vT_kernel() {
    __shared__ float ts[64 * 65];
    const int tid = threadIdx.x;
    const int t0 = blockIdx.x * 64, d0 = blockIdx.y * 64, b = blockIdx.z;

#pragma unroll
    for (int p = 0; p < 4; p++) {
        int idx = tid + p * 256;
        int r = idx >> 4, c4 = idx & 15;
        float4 v = *(const float4*)&g_v[((size_t)(b << 10) + t0 + r) * 256 + d0 + c4 * 4];
        ts[r * 65 + c4 * 4 + 0] = v.x; ts[r * 65 + c4 * 4 + 1] = v.y;
        ts[r * 65 + c4 * 4 + 2] = v.z; ts[r * 65 + c4 * 4 + 3] = v.w;
    }
    __syncthreads();
#pragma unroll
    for (int p = 0; p < 2; p++) {
        int idx = tid + p * 256;
        int dl = idx >> 3, tc = idx & 7;
        BP8 hp, lp;
#pragma unroll
        for (int j = 0; j < 8; j++) {
            float v = ts[(tc * 8 + j) * 65 + dl];
            hp.b[j] = __float2bfloat16_rn(v);
            lp.b[j] = __float2bfloat16_rn(v - __bfloat162float(hp.b[j]));
        }
        size_t di = ((size_t)b * 256 + d0 + dl) * 1024 + t0 + tc * 8;
        *(uint4*)&g_vth[di] = hp.u;
        *(uint4*)&g_vtl[di] = lp.u;
    }
}

// ============================================================================
extern "C" void kernel_launch(void* const* d_in, const int* in_sizes, int n_in,
                              void* d_out, int out_size) {
    const float* x  = (const float*)d_in[0];
    const float* Wq = (const float*)d_in[1];
    const float* bq = (const float*)d_in[2];
    const float* Wk = (const float*)d_in[3];
    const float* bk = (const float*)d_in[4];
    const float* Wv = (const float*)d_in[5];
    const float* bv = (const float*)d_in[6];
    float* out = (float*)d_out;

    void *axh, *axl, *awth, *awtl, *aqh, *aql, *akh, *akl, *avth, *avtl, *av, *aph, *apl;
    cudaGetSymbolAddress(&axh, g_xh);   cudaGetSymbolAddress(&axl, g_xl);
    cudaGetSymbolAddress(&awth, g_wth); cudaGetSymbolAddress(&awtl, g_wtl);
    cudaGetSymbolAddress(&aqh, g_qh);   cudaGetSymbolAddress(&aql, g_ql);
    cudaGetSymbolAddress(&akh, g_kh);   cudaGetSymbolAddress(&akl, g_kl);
    cudaGetSymbolAddress(&avth, g_vth); cudaGetSymbolAddress(&avtl, g_vtl);
    cudaGetSymbolAddress(&av, g_v);
    cudaGetSymbolAddress(&aph, g_ph);   cudaGetSymbolAddress(&apl, g_pl);

    cudaFuncSetAttribute(gemm3_mma<4, 256, 1>,
                         cudaFuncAttributeMaxDynamicSharedMemorySize, GSM_BYTES);
    cudaFuncSetAttribute(gemm3_mma<4, 1024, 2>,
                         cudaFuncAttributeMaxDynamicSharedMemorySize, GSM_BYTES);
    cudaFuncSetAttribute(gemm3_mma<16, 256, 3>,
                         cudaFuncAttributeMaxDynamicSharedMemorySize, GSM_BYTES);

    // 1. split inputs
    split_x_kernel<<<16384, 256>>>(x);
    splitT_w_kernel<<<dim3(4, 4, 3), 256>>>(Wq, Wk, Wv);

    // 2. QKV projection (bf16x3 HMMA): writes qh/ql, kh/kl, v
    gemm3_mma<4, 256, 1><<<dim3(512, 2, 3), 256, GSM_BYTES>>>(
        (const __nv_bfloat16*)axh, (const __nv_bfloat16*)axl,
        (const __nv_bfloat16*)awth, (const __nv_bfloat16*)awtl,
        nullptr, bq, bk, bv,
        0LL, 65536LL, 0LL, 256, 256);

    // 3. v -> vT hi/lo
    conv_vT_kernel<<<dim3(16, 4, 64), 256>>>();

    // 4. scores (bf16x3) + fused exp(s-60) + partial row sums -> g_ph/g_pl/g_lpart
    gemm3_mma<4, 1024, 2><<<dim3(8, 8, 64), 256, GSM_BYTES>>>(
        (const __nv_bfloat16*)aqh, (const __nv_bfloat16*)aql,
        (const __nv_bfloat16*)akh, (const __nv_bfloat16*)akl,
        nullptr, nullptr, nullptr, nullptr,
        262144LL, 262144LL, 0LL, 256, 256);

    // 5. row sums
    reduce_l_kernel<<<64, 256>>>();

    // 6. ctx = P @ v (bf16x3), normalized in epilogue -> out
    gemm3_mma<16, 256, 3><<<dim3(8, 2, 64), 256, GSM_BYTES>>>(
        (const __nv_bfloat16*)aph, (const __nv_bfloat16*)apl,
        (const __nv_bfloat16*)avth, (const __nv_bfloat16*)avtl,
        out, nullptr, nullptr, nullptr,
        1048576LL, 262144LL, 262144LL, 1024, 1024);
}

// round 12
// speedup vs baseline: 1.5654x; 1.2016x over previous
#include <cuda_runtime.h>
#include <cuda_bf16.h>
#include <math.h>
#include <stdint.h>

#define B_ 64
#define S_ 1024
#define E_ 256
#define NQK (64ull * 1024 * 256)
#define NP  (64ull * 1024 * 1024)

// -------------------- device scratch (static .bss, no runtime alloc) --------
__device__ __nv_bfloat16  g_xh [NQK], g_xl [NQK];     // x split [m][e]
__device__ __nv_bfloat16  g_wth[3 * 256 * 256], g_wtl[3 * 256 * 256];  // W^T split
__device__ __nv_bfloat16  g_qh [NQK], g_ql[NQK];
__device__ __nv_bfloat16  g_kh [NQK], g_kl[NQK];
__device__ __nv_bfloat16  g_vth[NQK], g_vtl[NQK];     // vT [b][d][t]
__device__ __nv_bfloat16  g_ph [NP];                  // bf16(exp(s-60)) [b][q][t]
__device__ float          g_lpart[64 * 16 * 1024];    // partial row sums [b][t16][q]
__device__ float          g_l  [64 * 1024];           // row sums [b][q]

union BP8 { __nv_bfloat16 b[8]; uint4 u; };
union BP4 { __nv_bfloat16 b[4]; uint2 u; };

// ---------------- base-target PTX helpers (sm_80+ features only) ------------
__device__ __forceinline__ uint32_t smem_u32(const void* p) {
    uint32_t a;
    asm("{ .reg .u64 t; cvta.to.shared.u64 t, %1; cvt.u32.u64 %0, t; }" : "=r"(a) : "l"(p));
    return a;
}
__device__ __forceinline__ void cpa16(uint32_t saddr, const void* g) {
    asm volatile("cp.async.cg.shared.global [%0], [%1], 16;" :: "r"(saddr), "l"(g));
}
#define CPA_COMMIT() asm volatile("cp.async.commit_group;" ::: "memory")
#define CPA_WAIT1()  asm volatile("cp.async.wait_group 1;" ::: "memory")
#define CPA_WAIT0()  asm volatile("cp.async.wait_group 0;" ::: "memory")

__device__ __forceinline__ void ldsm_x4(uint32_t* r, uint32_t addr) {
    asm volatile("ldmatrix.sync.aligned.m8n8.x4.shared.b16 {%0,%1,%2,%3}, [%4];"
                 : "=r"(r[0]), "=r"(r[1]), "=r"(r[2]), "=r"(r[3]) : "r"(addr));
}
__device__ __forceinline__ void mma16816(float* c, const uint32_t* a, const uint32_t* b) {
    asm volatile(
        "mma.sync.aligned.m16n8k16.row.col.f32.bf16.bf16.f32 "
        "{%0,%1,%2,%3}, {%4,%5,%6,%7}, {%8,%9}, {%0,%1,%2,%3};"
        : "+f"(c[0]), "+f"(c[1]), "+f"(c[2]), "+f"(c[3])
        : "r"(a[0]), "r"(a[1]), "r"(a[2]), "r"(a[3]), "r"(b[0]), "r"(b[1]));
}

__device__ __forceinline__ void store_hilo2(__nv_bfloat16* dh, __nv_bfloat16* dl,
                                            float a, float b) {
    __nv_bfloat16 ha = __float2bfloat16_rn(a), hb = __float2bfloat16_rn(b);
    __nv_bfloat162 hp; hp.x = ha; hp.y = hb;
    __nv_bfloat162 lp;
    lp.x = __float2bfloat16_rn(a - __bfloat162float(ha));
    lp.y = __float2bfloat16_rn(b - __bfloat162float(hb));
    *(__nv_bfloat162*)dh = hp;
    *(__nv_bfloat162*)dl = lp;
}

__device__ __forceinline__ float fast_exp(float x) {   // accurate over [-87, +40]
    float y = x * 1.4426950408889634f;
    float n = rintf(y);
    float t = (y - n) * 0.6931471805599453f;
    float p = 1.9841270e-4f;
    p = fmaf(p, t, 1.3888889e-3f);
    p = fmaf(p, t, 8.3333333e-3f);
    p = fmaf(p, t, 4.1666667e-2f);
    p = fmaf(p, t, 0.16666667f);
    p = fmaf(p, t, 0.5f);
    p = fmaf(p, t, 1.0f);
    p = fmaf(p, t, 1.0f);
    float r = __int_as_float(__float_as_int(p) + ((int)n << 23));
    return (x > -87.0f) ? r : 0.0f;
}

// ============================================================================
// bf16 multi-term HMMA GEMM.  NTERMS=3: Ah.Bh^T + Ah.Bl^T + Al.Bh^T
//                             NTERMS=2: Ah.Bh^T + Ah.Bl^T   (Al unused)
// CTA tile 128x128, k-chunk 64, 8 warps (4m x 2n), cp.async double-buffered.
// EPI 1: proj epilogue (bias + hi/lo split q,k; z==2: transpose -> vT hi/lo)
// EPI 2: scores epilogue (bf16(exp(s-60)) + deterministic rounded row sums)
// EPI 3: AV epilogue (divide by row sum, store to out)
// ============================================================================
#define GSM_BYTES (2 * 65536 + 128)

template<int NCH, int NTOT, int EPI, int NTERMS>
__global__ __launch_bounds__(256) void gemm3_mma(
    const __nv_bfloat16* __restrict__ Ah_, const __nv_bfloat16* __restrict__ Al_,
    const __nv_bfloat16* __restrict__ Bh_, const __nv_bfloat16* __restrict__ Bl_,
    float* __restrict__ C,
    const float* __restrict__ bq, const float* __restrict__ bk,
    const float* __restrict__ bv,
    long long aBatch, long long bBatch, long long cBatch, int lda, int ldb) {
    extern __shared__ char dsm[];
    char* sb = (char*)(((uintptr_t)dsm + 127) & ~(uintptr_t)127);
    const uint32_t sbase = smem_u32(sb);

    const int tid = threadIdx.x;
    const int wid = tid >> 5, lane = tid & 31;
    const int z = blockIdx.z;
    const int m0 = blockIdx.x * 128, n0 = blockIdx.y * 128;

    const __nv_bfloat16* gA[2] = { Ah_ + (size_t)z * aBatch + (size_t)m0 * lda,
                                   Al_ + (size_t)z * aBatch + (size_t)m0 * lda };
    const __nv_bfloat16* gB[2] = { Bh_ + (size_t)z * bBatch + (size_t)n0 * ldb,
                                   Bl_ + (size_t)z * bBatch + (size_t)n0 * ldb };

    const int lrow = tid >> 3, lkg = tid & 7;

    const int wm = wid & 3, wn = wid >> 2;
    const int li = lane >> 3, lr = lane & 7;
    const int arow = wm * 32 + (li & 1) * 8 + lr;
    const int brow = wn * 64 + (li & 1) * 8 + lr;
    const int kgh = li >> 1;

    float acc[2][8][4];
#pragma unroll
    for (int im = 0; im < 2; im++)
#pragma unroll
        for (int j = 0; j < 8; j++)
#pragma unroll
            for (int q = 0; q < 4; q++) acc[im][j][q] = 0.0f;

#define LOAD_STAGE(kc, st) do {                                                  \
        uint32_t s0_ = sbase + (st) * 65536;                                     \
        _Pragma("unroll")                                                        \
        for (int m_ = 0; m_ < 4; m_++) {                                         \
            if (NTERMS == 2 && m_ == 1) continue;                                \
            const __nv_bfloat16* src_ = (m_ < 2) ? gA[m_] : gB[m_ - 2];          \
            int ld_ = (m_ < 2) ? lda : ldb;                                      \
            _Pragma("unroll")                                                    \
            for (int p_ = 0; p_ < 4; p_++) {                                     \
                int row_ = lrow + p_ * 32;                                       \
                cpa16(s0_ + m_ * 16384 + row_ * 128 + ((lkg ^ (row_ & 7)) << 4), \
                      src_ + (size_t)row_ * ld_ + (kc) * 64 + lkg * 8);          \
            }                                                                    \
        }                                                                        \
    } while (0)

    LOAD_STAGE(0, 0); CPA_COMMIT();
    LOAD_STAGE(1, 1); CPA_COMMIT();

    for (int kc = 0; kc < NCH; kc++) {
        CPA_WAIT1();
        __syncthreads();
        const uint32_t s0 = sbase + (kc & 1) * 65536;
#pragma unroll
        for (int kt = 0; kt < 4; kt++) {
            const int kg = kt * 2 + kgh;
            uint32_t ah[2][4], al[2][4], bh[4][4], bl[4][4];
#pragma unroll
            for (int im = 0; im < 2; im++) {
                int m_l = arow + im * 16;
                uint32_t ad = s0 + m_l * 128 + ((kg ^ (m_l & 7)) << 4);
                ldsm_x4(ah[im], ad);
                if (NTERMS == 3) ldsm_x4(al[im], ad + 16384);
            }
#pragma unroll
            for (int jn = 0; jn < 4; jn++) {
                int n_l = brow + jn * 16;
                uint32_t bd = s0 + 32768 + n_l * 128 + ((kg ^ (n_l & 7)) << 4);
                ldsm_x4(bh[jn], bd);
                ldsm_x4(bl[jn], bd + 16384);
            }
#pragma unroll
            for (int im = 0; im < 2; im++)
#pragma unroll
                for (int j8 = 0; j8 < 8; j8++) {
                    uint32_t bfh[2] = { bh[j8 >> 1][j8 & 1], bh[j8 >> 1][(j8 & 1) + 2] };
                    uint32_t bfl[2] = { bl[j8 >> 1][j8 & 1], bl[j8 >> 1][(j8 & 1) + 2] };
                    mma16816(acc[im][j8], ah[im], bfh);
                    mma16816(acc[im][j8], ah[im], bfl);
                    if (NTERMS == 3) mma16816(acc[im][j8], al[im], bfh);
                }
        }
        __syncthreads();
        if (kc + 2 < NCH) LOAD_STAGE(kc + 2, kc & 1);
        CPA_COMMIT();
    }
#undef LOAD_STAGE

    const int erow = wm * 32 + (lane >> 2);
    const int ecol = wn * 64 + 2 * (lane & 3);

    if (EPI == 1) {
        // -------- projection epilogue --------
        const float* bias = (z == 0) ? bq : (z == 1) ? bk : bv;
        if (z == 2) {
            // v: stage fp32 tile in SMEM, then split+store transposed -> vT
            CPA_WAIT0();
            __syncthreads();
            float* ts = (float*)sb;   // [128][pitch 130]
#pragma unroll
            for (int im = 0; im < 2; im++)
#pragma unroll
                for (int j8 = 0; j8 < 8; j8++) {
                    int rl = erow + im * 16;
                    int cl = ecol + j8 * 8;
                    float b0v = bias[n0 + cl], b1v = bias[n0 + cl + 1];
                    ts[rl * 130 + cl]           = acc[im][j8][0] + b0v;
                    ts[rl * 130 + cl + 1]       = acc[im][j8][1] + b1v;
                    ts[(rl + 8) * 130 + cl]     = acc[im][j8][2] + b0v;
                    ts[(rl + 8) * 130 + cl + 1] = acc[im][j8][3] + b1v;
                }
            __syncthreads();
            const int dl = tid >> 1;
            const int bb = m0 >> 10, tt0 = m0 & 1023;
#pragma unroll
            for (int p = 0; p < 8; p++) {
                int t0l = ((tid & 1) + 2 * p) * 8;
                BP8 hp, lp;
#pragma unroll
                for (int j = 0; j < 8; j++) {
                    float v = ts[(t0l + j) * 130 + dl];
                    hp.b[j] = __float2bfloat16_rn(v);
                    lp.b[j] = __float2bfloat16_rn(v - __bfloat162float(hp.b[j]));
                }
                size_t di = ((size_t)bb * 256 + n0 + dl) * 1024 + tt0 + t0l;
                *(uint4*)&g_vth[di] = hp.u;
                *(uint4*)&g_vtl[di] = lp.u;
            }
        } else {
#pragma unroll
            for (int im = 0; im < 2; im++)
#pragma unroll
                for (int j8 = 0; j8 < 8; j8++) {
                    int rr = m0 + erow + im * 16;
                    int cc = n0 + ecol + j8 * 8;
                    float b0v = bias[cc], b1v = bias[cc + 1];
                    float v00 = acc[im][j8][0] + b0v, v01 = acc[im][j8][1] + b1v;
                    float v10 = acc[im][j8][2] + b0v, v11 = acc[im][j8][3] + b1v;
                    __nv_bfloat16* dh = (z == 0) ? g_qh : g_kh;
                    __nv_bfloat16* dl = (z == 0) ? g_ql : g_kl;
                    store_hilo2(dh + (size_t)rr * 256 + cc, dl + (size_t)rr * 256 + cc, v00, v01);
                    store_hilo2(dh + (size_t)(rr + 8) * 256 + cc, dl + (size_t)(rr + 8) * 256 + cc, v10, v11);
                }
        }
    } else if (EPI == 2) {
        // ---- scores epilogue: P = bf16(exp(s-60)); row sums of ROUNDED P ----
        float srow[4] = { 0.0f, 0.0f, 0.0f, 0.0f };
#pragma unroll
        for (int im = 0; im < 2; im++)
#pragma unroll
            for (int j8 = 0; j8 < 8; j8++) {
                int rr = m0 + erow + im * 16;
                int cc = n0 + ecol + j8 * 8;
                __nv_bfloat16 h0 = __float2bfloat16_rn(fast_exp(acc[im][j8][0] - 60.0f));
                __nv_bfloat16 h1 = __float2bfloat16_rn(fast_exp(acc[im][j8][1] - 60.0f));
                __nv_bfloat16 h2 = __float2bfloat16_rn(fast_exp(acc[im][j8][2] - 60.0f));
                __nv_bfloat16 h3 = __float2bfloat16_rn(fast_exp(acc[im][j8][3] - 60.0f));
                size_t o0 = ((size_t)(z << 10) + rr) * 1024 + cc;
                size_t o8 = o0 + 8 * 1024;
                __nv_bfloat162 p01; p01.x = h0; p01.y = h1;
                __nv_bfloat162 p23; p23.x = h2; p23.y = h3;
                *(__nv_bfloat162*)&g_ph[o0] = p01;
                *(__nv_bfloat162*)&g_ph[o8] = p23;
                srow[im * 2 + 0] += __bfloat162float(h0) + __bfloat162float(h1);
                srow[im * 2 + 1] += __bfloat162float(h2) + __bfloat162float(h3);
            }
#pragma unroll
        for (int r4 = 0; r4 < 4; r4++) {
            float s = srow[r4];
            s += __shfl_xor_sync(0xffffffffu, s, 1);
            s += __shfl_xor_sync(0xffffffffu, s, 2);
            if ((lane & 3) == 0) {
                int row = m0 + erow + (r4 >> 1) * 16 + (r4 & 1) * 8;
                g_lpart[(((size_t)z * 16 + (n0 >> 6) + wn) << 10) + row] = s;
            }
        }
    } else {
        // -------- AV epilogue: normalize by row sum, store ctx ---------------
        float linv[4];
#pragma unroll
        for (int r4 = 0; r4 < 4; r4++)
            linv[r4] = 1.0f / g_l[(size_t)(z << 10) + m0 + erow + (r4 >> 1) * 16 + (r4 & 1) * 8];
        float* Cb = C + (size_t)z * cBatch;
#pragma unroll
        for (int im = 0; im < 2; im++)
#pragma unroll
            for (int j8 = 0; j8 < 8; j8++) {
                int rr = m0 + erow + im * 16;
                int cc = n0 + ecol + j8 * 8;
                *(float2*)&Cb[(size_t)rr * NTOT + cc] =
                    make_float2(acc[im][j8][0] * linv[im * 2], acc[im][j8][1] * linv[im * 2]);
                *(float2*)&Cb[(size_t)(rr + 8) * NTOT + cc] =
                    make_float2(acc[im][j8][2] * linv[im * 2 + 1], acc[im][j8][3] * linv[im * 2 + 1]);
            }
    }
}

// ============================================================================
// reduce partial row sums: g_l[b][q] = sum_16 g_lpart[b][t][q]
// ============================================================================
__global__ __launch_bounds__(256) void reduce_l_kernel() {
    const int b = blockIdx.x;
#pragma unroll
    for (int p = 0; p < 4; p++) {
        int r = threadIdx.x + p * 256;
        float s = 0.0f;
#pragma unroll
        for (int t = 0; t < 16; t++)
            s += g_lpart[(((size_t)b * 16 + t) << 10) + r];
        g_l[((size_t)b << 10) + r] = s;
    }
}

// ============================================================================
// split x -> bf16 hi/lo
// ============================================================================
__global__ __launch_bounds__(256) void split_x_kernel(const float* __restrict__ x) {
    size_t i = ((size_t)blockIdx.x * 256 + threadIdx.x) * 4;
    float4 v = *(const float4*)&x[i];
    float f[4] = { v.x, v.y, v.z, v.w };
    BP4 hp, lp;
#pragma unroll
    for (int j = 0; j < 4; j++) {
        hp.b[j] = __float2bfloat16_rn(f[j]);
        lp.b[j] = __float2bfloat16_rn(f[j] - __bfloat162float(hp.b[j]));
    }
    *(uint2*)&g_xh[i] = hp.u;
    *(uint2*)&g_xl[i] = lp.u;
}

// ============================================================================
// transpose + split W (256x256, [e][n] -> [n][e] hi/lo), z = which W
// ============================================================================
__global__ __launch_bounds__(256) void splitT_w_kernel(
    const float* __restrict__ Wq, const float* __restrict__ Wk,
    const float* __restrict__ Wv) {
    __shared__ float ts[64 * 65];
    const float* W = (blockIdx.z == 0) ? Wq : (blockIdx.z == 1) ? Wk : Wv;
    const int e0 = blockIdx.x * 64, n0 = blockIdx.y * 64;
    const int tid = threadIdx.x;
    const size_t zo = (size_t)blockIdx.z * 65536;

#pragma unroll
    for (int p = 0; p < 4; p++) {
        int idx = tid + p * 256;
        int r = idx >> 4, c4 = idx & 15;
        float4 v = *(const float4*)&W[(size_t)(e0 + r) * 256 + n0 + c4 * 4];
        ts[r * 65 + c4 * 4 + 0] = v.x; ts[r * 65 + c4 * 4 + 1] = v.y;
        ts[r * 65 + c4 * 4 + 2] = v.z; ts[r * 65 + c4 * 4 + 3] = v.w;
    }
    __syncthreads();
#pragma unroll
    for (int p = 0; p < 2; p++) {
        int idx = tid + p * 256;
        int nl = idx >> 3, tc = idx & 7;
        BP8 hp, lp;
#pragma unroll
        for (int j = 0; j < 8; j++) {
            float v = ts[(tc * 8 + j) * 65 + nl];
            hp.b[j] = __float2bfloat16_rn(v);
            lp.b[j] = __float2bfloat16_rn(v - __bfloat162float(hp.b[j]));
        }
        size_t di = zo + (size_t)(n0 + nl) * 256 + e0 + tc * 8;
        *(uint4*)&g_wth[di] = hp.u;
        *(uint4*)&g_wtl[di] = lp.u;
    }
}

// ============================================================================
extern "C" void kernel_launch(void* const* d_in, const int* in_sizes, int n_in,
                              void* d_out, int out_size) {
    const float* x  = (const float*)d_in[0];
    const float* Wq = (const float*)d_in[1];
    const float* bq = (const float*)d_in[2];
    const float* Wk = (const float*)d_in[3];
    const float* bk = (const float*)d_in[4];
    const float* Wv = (const float*)d_in[5];
    const float* bv = (const float*)d_in[6];
    float* out = (float*)d_out;

    void *axh, *axl, *awth, *awtl, *aqh, *aql, *akh, *akl, *avth, *avtl, *aph;
    cudaGetSymbolAddress(&axh, g_xh);   cudaGetSymbolAddress(&axl, g_xl);
    cudaGetSymbolAddress(&awth, g_wth); cudaGetSymbolAddress(&awtl, g_wtl);
    cudaGetSymbolAddress(&aqh, g_qh);   cudaGetSymbolAddress(&aql, g_ql);
    cudaGetSymbolAddress(&akh, g_kh);   cudaGetSymbolAddress(&akl, g_kl);
    cudaGetSymbolAddress(&avth, g_vth); cudaGetSymbolAddress(&avtl, g_vtl);
    cudaGetSymbolAddress(&aph, g_ph);

    cudaFuncSetAttribute(gemm3_mma<4, 256, 1, 3>,
                         cudaFuncAttributeMaxDynamicSharedMemorySize, GSM_BYTES);
    cudaFuncSetAttribute(gemm3_mma<4, 1024, 2, 3>,
                         cudaFuncAttributeMaxDynamicSharedMemorySize, GSM_BYTES);
    cudaFuncSetAttribute(gemm3_mma<16, 256, 3, 2>,
                         cudaFuncAttributeMaxDynamicSharedMemorySize, GSM_BYTES);

    // 1. split inputs
    split_x_kernel<<<16384, 256>>>(x);
    splitT_w_kernel<<<dim3(4, 4, 3), 256>>>(Wq, Wk, Wv);

    // 2. QKV projection (bf16x3 HMMA): q,k hi/lo; v transposed hi/lo (vT)
    gemm3_mma<4, 256, 1, 3><<<dim3(512, 2, 3), 256, GSM_BYTES>>>(
        (const __nv_bfloat16*)axh, (const __nv_bfloat16*)axl,
        (const __nv_bfloat16*)awth, (const __nv_bfloat16*)awtl,
        nullptr, bq, bk, bv,
        0LL, 65536LL, 0LL, 256, 256);

    // 3. scores (bf16x3) + fused exp(s-60) + rounded partial row sums
    gemm3_mma<4, 1024, 2, 3><<<dim3(8, 8, 64), 256, GSM_BYTES>>>(
        (const __nv_bfloat16*)aqh, (const __nv_bfloat16*)aql,
        (const __nv_bfloat16*)akh, (const __nv_bfloat16*)akl,
        nullptr, nullptr, nullptr, nullptr,
        262144LL, 262144LL, 0LL, 256, 256);

    // 4. row sums
    reduce_l_kernel<<<64, 256>>>();

    // 5. ctx = Ph @ (Vh + Vl) (2-term), normalized in epilogue -> out
    gemm3_mma<16, 256, 3, 2><<<dim3(8, 2, 64), 256, GSM_BYTES>>>(
        (const __nv_bfloat16*)aph, (const __nv_bfloat16*)aph,
        (const __nv_bfloat16*)avth, (const __nv_bfloat16*)avtl,
        out, nullptr, nullptr, nullptr,
        1048576LL, 262144LL, 262144LL, 1024, 1024);
}